// round 11
// baseline (speedup 1.0000x reference)
#include <cuda_runtime.h>
#include <cuda_bf16.h>
#include <cstddef>
#include <cstdint>

#define NBATCH 64
#define LSEQ   256
#define LASP   8
#define EMB    300
#define KP     320
#define HID    384
#define G4     1536
#define DFEAT  768
#define FIN    768
#define NCLS   3
#define SROWS  (NBATCH*LSEQ)
#define AROWS  (NBATCH*LASP)
#define MROWS  (SROWS+AROWS)

// ---------------- device scratch (static; no runtime allocation) ----------------
__device__ float g_X[MROWS * KP];
__device__ float g_xg[2 * MROWS * G4];
__device__ float g_Wt[2 * KP * G4];
__device__ float g_bias[2 * G4];
__device__ float g_W1t[FIN * FIN];
__device__ float g_W2t[FIN * FIN];
__device__ float g_Wft[FIN * 128];
__device__ float g_feat[(size_t)SROWS * DFEAT];
__device__ float g_h[2 * 2 * NBATCH * HID];
__device__ float g_aspv[NBATCH * DFEAT];
__device__ float g_dot[NBATCH * LSEQ];
__device__ float g_att[NBATCH * LSEQ];
__device__ float g_pool[NBATCH * DFEAT];
__device__ float g_x1[NBATCH * FIN];
__device__ float g_x2[NBATCH * FIN];
__device__ float g_logits[NBATCH * NCLS];
__device__ unsigned int g_bar;

__device__ __forceinline__ float sigf(float x) { return 1.0f / (1.0f + __expf(-x)); }

// packed f32x2 FMA (Blackwell FFMA2 — only reachable via PTX)
__device__ __forceinline__ void fma2(unsigned long long& acc, unsigned long long a,
                                     unsigned long long b) {
    asm("fma.rn.f32x2 %0, %1, %2, %0;" : "+l"(acc) : "l"(a), "l"(b));
}
__device__ __forceinline__ unsigned long long pack2(float lo, float hi) {
    unsigned long long r;
    asm("mov.b64 %0, {%1, %2};" : "=l"(r) : "f"(lo), "f"(hi));
    return r;
}
__device__ __forceinline__ float2 unpack2(unsigned long long v) {
    float2 r;
    asm("mov.b64 {%0, %1}, %2;" : "=f"(r.x), "=f"(r.y) : "l"(v));
    return r;
}

// relaxed ATOMIC load (morally strong; valid flag observation for
// fence/fence synchronization, but a plain read at the LTS — no RMW)
__device__ __forceinline__ unsigned int ld_relaxed_u32(const unsigned int* p) {
    unsigned int v;
    asm volatile("ld.global.relaxed.gpu.u32 %0, [%1];" : "=r"(v) : "l"(p));
    return v;
}

// cp.async helpers
__device__ __forceinline__ void cp_async16(uint32_t dst, const void* src) {
    asm volatile("cp.async.cg.shared.global [%0], [%1], 16;\n" :: "r"(dst), "l"(src));
}
__device__ __forceinline__ void cp_commit() { asm volatile("cp.async.commit_group;\n" ::: "memory"); }
template<int N> __device__ __forceinline__ void cp_wait() {
    asm volatile("cp.async.wait_group %0;\n" :: "n"(N) : "memory");
}

// ---------------- prep: weight transposes, bias sums, barrier reset ----------------
__global__ void k_prep(const float* __restrict__ wih_f, const float* __restrict__ wih_b,
                       const float* __restrict__ bih_f, const float* __restrict__ bhh_f,
                       const float* __restrict__ bih_b, const float* __restrict__ bhh_b,
                       const float* __restrict__ W1, const float* __restrict__ W2,
                       const float* __restrict__ Wf)
{
    int tid = blockIdx.x * blockDim.x + threadIdx.x;
    int stride = gridDim.x * blockDim.x;
    for (int i = tid; i < 2 * KP * G4; i += stride) {
        int d = i / (KP * G4);
        int r = i - d * (KP * G4);
        int k = r / G4, g = r - (r / G4) * G4;
        const float* w = d ? wih_b : wih_f;
        g_Wt[i] = (k < EMB) ? w[g * EMB + k] : 0.0f;
    }
    for (int i = tid; i < 2 * G4; i += stride) {
        int d = i / G4, g = i - d * G4;
        g_bias[i] = d ? (bih_b[g] + bhh_b[g]) : (bih_f[g] + bhh_f[g]);
    }
    for (int i = tid; i < FIN * FIN; i += stride) {
        int k = i / FIN, n = i - (i / FIN) * FIN;
        g_W1t[i] = W1[n * FIN + k];
        g_W2t[i] = W2[n * FIN + k];
    }
    for (int i = tid; i < FIN * 128; i += stride) {
        int k = i / 128, c = i - (i / 128) * 128;
        g_Wft[i] = (c < NCLS) ? Wf[c * FIN + k] : 0.0f;
    }
    if (tid == 0) g_bar = 0u;
}

// ---------------- gather embeddings (padded) + zero h state ----------------
__global__ void k_gather(const int* __restrict__ sentence, const int* __restrict__ aspect,
                         const float* __restrict__ emb)
{
    int tid = blockIdx.x * blockDim.x + threadIdx.x;
    int stride = gridDim.x * blockDim.x;
    for (int i = tid; i < MROWS * KP; i += stride) {
        int row = i / KP, k = i - row * KP;
        int tok = (row < SROWS) ? sentence[row] : aspect[row - SROWS];
        g_X[i] = (k < EMB) ? emb[(size_t)tok * EMB + k] : 0.0f;
    }
    for (int i = tid; i < 2 * 2 * NBATCH * HID; i += stride) g_h[i] = 0.0f;
}

// ---------------- fp32 GEMM 128x128x16, reg-prefetch + FFMA2 ----------------
#define BM 128
#define BN 128
#define BK 16

__global__ void __launch_bounds__(256) k_gemm(
    const float* __restrict__ A, int lda,
    const float* __restrict__ Bt, int ldb,
    const float* __restrict__ bias,
    float* __restrict__ C, int ldc,
    int M, int Nn, int K, int relu)
{
    __shared__ float As[BK][BM + 4];
    __shared__ float Bs[BK][BN + 4];
    int t = threadIdx.x;
    int tx = t & 15, ty = t >> 4;
    int m0 = blockIdx.x * BM, n0 = blockIdx.y * BN;
    unsigned long long acc2[8][4];
#pragma unroll
    for (int i = 0; i < 8; i++)
#pragma unroll
        for (int j = 0; j < 4; j++) acc2[i][j] = 0ull;

    int arow[2], akq[2], bkk[2], bnq[2];
#pragma unroll
    for (int q = 0; q < 2; q++) {
        int f = t + 256 * q;
        arow[q] = f >> 2;  akq[q] = (f & 3) * 4;
        bkk[q]  = f >> 5;  bnq[q] = (f & 31) * 4;
    }

    int nkt = K / BK;
    float4 av[2], bv[2];
    {
#pragma unroll
        for (int q = 0; q < 2; q++) {
            int gm = m0 + arow[q];
            av[q] = (gm < M) ? *(const float4*)(A + (size_t)gm * lda + akq[q])
                             : make_float4(0.f, 0.f, 0.f, 0.f);
            bv[q] = *(const float4*)(Bt + (size_t)bkk[q] * ldb + n0 + bnq[q]);
        }
    }

    for (int kt = 0; kt < nkt; ++kt) {
        __syncthreads();
#pragma unroll
        for (int q = 0; q < 2; q++) {
            As[akq[q] + 0][arow[q]] = av[q].x; As[akq[q] + 1][arow[q]] = av[q].y;
            As[akq[q] + 2][arow[q]] = av[q].z; As[akq[q] + 3][arow[q]] = av[q].w;
            *(float4*)&Bs[bkk[q]][bnq[q]] = bv[q];
        }
        __syncthreads();

        if (kt + 1 < nkt) {
            int k0 = (kt + 1) * BK;
#pragma unroll
            for (int q = 0; q < 2; q++) {
                int gm = m0 + arow[q];
                av[q] = (gm < M) ? *(const float4*)(A + (size_t)gm * lda + k0 + akq[q])
                                 : make_float4(0.f, 0.f, 0.f, 0.f);
                bv[q] = *(const float4*)(Bt + (size_t)(k0 + bkk[q]) * ldb + n0 + bnq[q]);
            }
        }

#pragma unroll
        for (int k = 0; k < BK; k++) {
            ulonglong2 b0 = *(ulonglong2*)&Bs[k][tx * 4];
            ulonglong2 b1 = *(ulonglong2*)&Bs[k][tx * 4 + 64];
            unsigned long long bp[4] = {b0.x, b0.y, b1.x, b1.y};
            float4 a0 = *(float4*)&As[k][ty * 8];
            float4 a1 = *(float4*)&As[k][ty * 8 + 4];
            float a[8] = {a0.x, a0.y, a0.z, a0.w, a1.x, a1.y, a1.z, a1.w};
#pragma unroll
            for (int i = 0; i < 8; i++) {
                unsigned long long as = pack2(a[i], a[i]);
#pragma unroll
                for (int j = 0; j < 4; j++)
                    fma2(acc2[i][j], as, bp[j]);
            }
        }
    }
#pragma unroll
    for (int i = 0; i < 8; i++) {
        int gm = m0 + ty * 8 + i;
        if (gm < M) {
#pragma unroll
            for (int jp = 0; jp < 4; jp++) {
                float2 p = unpack2(acc2[i][jp]);
                int col = tx * 4 + (jp < 2 ? jp * 2 : 64 + (jp - 2) * 2);
#pragma unroll
                for (int e = 0; e < 2; e++) {
                    int gn = n0 + col + e;
                    if (gn < Nn) {
                        float v = e ? p.y : p.x;
                        if (bias) v += bias[gn];
                        if (relu) v = fmaxf(v, 0.0f);
                        C[(size_t)gm * ldc + gn] = v;
                    }
                }
            }
        }
    }
}

// ---------------- persistent BiLSTM recurrence ----------------
#define HSTR 388
#define WSTR 400

__global__ void __launch_bounds__(256, 1) k_recur(const float* __restrict__ whhf,
                                                  const float* __restrict__ whhb)
{
    extern __shared__ float sm[];
    float* Ws   = sm;                    // 24*400
    float* Hs   = Ws + 24 * WSTR;        // 64*388
    float* Gs   = Hs + 64 * HSTR;        // 64*25
    float* Xs   = Gs + 64 * 25;          // 64*25
    float* Cs   = Xs + 64 * 25;          // 64*6
    float* Asum = Cs + 64 * 6;           // 64*6

    const int t = threadIdx.x;
    const int cta = blockIdx.x;
    const int dir = cta >> 6;
    const int slice = cta & 63;
    const int u0 = slice * 6;
    const float* whh = dir ? whhb : whhf;
    const float* xgbase = g_xg + (size_t)dir * MROWS * G4;

    const int kt = t & 3, rt = (t >> 2) & 3, ntid = t >> 4;
    const int n0 = ntid * 4;

    for (int i = t; i < 24 * HID; i += 256) {
        int lr = i / HID, k = i - lr * HID;
        int gate = lr & 3, u = lr >> 2;
        Ws[lr * WSTR + k] = whh[(size_t)(gate * HID + u0 + u) * HID + k];
    }
    if (t < 64) {
#pragma unroll
        for (int u = 0; u < 6; u++) { Cs[t * 6 + u] = 0.0f; Asum[t * 6 + u] = 0.0f; }
    }
    __syncthreads();

    int srows[6], scols[6];
    uint32_t sdst[6];
    uint32_t HsU = (uint32_t)__cvta_generic_to_shared(Hs);
#pragma unroll
    for (int p = 0; p < 6; p++) {
        int idx = t + 256 * p;
        srows[p] = idx / 24;
        scols[p] = idx - srows[p] * 24;
        sdst[p] = HsU + (uint32_t)(srows[p] * HSTR + scols[p] * 4) * 4u;
    }
    const int xn = t >> 2, xgate = t & 3;

    int nb = 0;
    unsigned int tgt = 0;

    for (int phase = 0; phase < 2; ++phase) {
        const int T = phase ? LASP : LSEQ;
        for (int s = 0; s < T; ++s) {
            const int tt = dir ? (T - 1 - s) : s;

            const float* hsrc = g_h + ((size_t)(nb * 2 + dir)) * NBATCH * HID;
#pragma unroll
            for (int c = 0; c < 4; c++) {
#pragma unroll
                for (int p = 0; p < 6; p++) {
                    const float* src = hsrc + srows[p] * HID + (c * 24 + scols[p]) * 4;
                    cp_async16(sdst[p] + (uint32_t)(c * 24 * 16), src);
                }
                cp_commit();
            }

            {
                size_t row = phase ? (size_t)(SROWS + xn * LASP + tt) : (size_t)(xn * LSEQ + tt);
                const float* xp = xgbase + row * G4 + xgate * HID + u0;
#pragma unroll
                for (int j = 0; j < 6; j++) Xs[xn * 25 + xgate * 6 + j] = xp[j];
            }

            unsigned long long acc2[4][6];
#pragma unroll
            for (int i = 0; i < 4; i++)
#pragma unroll
                for (int j = 0; j < 6; j++) acc2[i][j] = 0ull;

#pragma unroll
            for (int c = 0; c < 4; c++) {
                if (c == 0) cp_wait<3>();
                else if (c == 1) cp_wait<2>();
                else if (c == 2) cp_wait<1>();
                else cp_wait<0>();
                __syncthreads();
#pragma unroll
                for (int it2 = 0; it2 < 6; it2++) {
                    int fk = (c * 24 + it2 * 4 + kt) * 4;
                    ulonglong2 hv[4], wv[6];
#pragma unroll
                    for (int i = 0; i < 4; i++)
                        hv[i] = *(const ulonglong2*)&Hs[(n0 + i) * HSTR + fk];
#pragma unroll
                    for (int j = 0; j < 6; j++)
                        wv[j] = *(const ulonglong2*)&Ws[(j * 4 + rt) * WSTR + fk];
#pragma unroll
                    for (int i = 0; i < 4; i++)
#pragma unroll
                        for (int j = 0; j < 6; j++) {
                            fma2(acc2[i][j], hv[i].x, wv[j].x);
                            fma2(acc2[i][j], hv[i].y, wv[j].y);
                        }
                }
            }

#pragma unroll
            for (int i = 0; i < 4; i++)
#pragma unroll
                for (int j = 0; j < 6; j++) {
                    float2 pp = unpack2(acc2[i][j]);
                    float v = pp.x + pp.y;
                    v += __shfl_xor_sync(0xFFFFFFFFu, v, 1);
                    v += __shfl_xor_sync(0xFFFFFFFFu, v, 2);
                    if (kt == 0) Gs[(n0 + i) * 25 + rt * 6 + j] = v;
                }
            __syncthreads();

            if (t < 64) {
                int n2 = t;
                float* hout = g_h + ((size_t)(((nb ^ 1) * 2 + dir)) * NBATCH * HID) + n2 * HID + u0;
#pragma unroll
                for (int u = 0; u < 6; u++) {
                    float gi = Gs[n2 * 25 + u]      + Xs[n2 * 25 + u];
                    float gf = Gs[n2 * 25 + 6 + u]  + Xs[n2 * 25 + 6 + u];
                    float gg = Gs[n2 * 25 + 12 + u] + Xs[n2 * 25 + 12 + u];
                    float go = Gs[n2 * 25 + 18 + u] + Xs[n2 * 25 + 18 + u];
                    float c = sigf(gf) * Cs[n2 * 6 + u] + sigf(gi) * tanhf(gg);
                    float h = sigf(go) * tanhf(c);
                    Cs[n2 * 6 + u] = c;
                    hout[u] = h;
                    if (phase == 0)
                        g_feat[(size_t)(n2 * LSEQ + tt) * DFEAT + dir * HID + u0 + u] = h;
                    else
                        Asum[n2 * 6 + u] += h;
                }
                __threadfence();
            }
            __syncthreads();
            tgt += 128;
            if (t == 0) {
                __threadfence();
                atomicAdd(&g_bar, 1u);
                while (ld_relaxed_u32(&g_bar) < tgt) { }
                __threadfence();
            }
            __syncthreads();
            nb ^= 1;
        }
        if (phase == 0) {
            if (t < 64) {
                float* hout = g_h + ((size_t)(nb * 2 + dir)) * NBATCH * HID + t * HID + u0;
#pragma unroll
                for (int u = 0; u < 6; u++) { hout[u] = 0.0f; Cs[t * 6 + u] = 0.0f; }
                __threadfence();
            }
            __syncthreads();
            tgt += 128;
            if (t == 0) {
                __threadfence();
                atomicAdd(&g_bar, 1u);
                while (ld_relaxed_u32(&g_bar) < tgt) { }
                __threadfence();
            }
            __syncthreads();
        }
    }
    if (t < 64) {
#pragma unroll
        for (int u = 0; u < 6; u++)
            g_aspv[t * DFEAT + dir * HID + u0 + u] = Asum[t * 6 + u] * (1.0f / LASP);
    }
}

// ---------------- attention: dots ----------------
__global__ void k_dots()
{
    __shared__ float As2[DFEAT];
    int n = blockIdx.x;
    for (int i = threadIdx.x; i < DFEAT; i += 256) As2[i] = g_aspv[n * DFEAT + i];
    __syncthreads();
    int warp = threadIdx.x >> 5, lane = threadIdx.x & 31;
    int l = blockIdx.y * 8 + warp;
    const float* f = g_feat + (size_t)(n * LSEQ + l) * DFEAT;
    float s = 0.0f;
    for (int i = lane * 4; i < DFEAT; i += 128) {
        float4 fv = *(const float4*)(f + i);
        float4 av = *(const float4*)(&As2[i]);
        s += fv.x * av.x + fv.y * av.y + fv.z * av.z + fv.w * av.w;
    }
#pragma unroll
    for (int o = 16; o; o >>= 1) s += __shfl_xor_sync(0xFFFFFFFFu, s, o);
    if (lane == 0) g_dot[n * LSEQ + l] = s;
}

// ---------------- masked softmax over L ----------------
__global__ void k_softmax(const int* __restrict__ tl)
{
    __shared__ float redm[8];
    __shared__ float reds[8];
    int n = blockIdx.x, t = threadIdx.x;
    int len = tl[n];
    float d = g_dot[n * LSEQ + t];
    float v = (t < len) ? d : -1e30f;
    float m = v;
#pragma unroll
    for (int o = 16; o; o >>= 1) m = fmaxf(m, __shfl_xor_sync(0xFFFFFFFFu, m, o));
    if ((t & 31) == 0) redm[t >> 5] = m;
    __syncthreads();
    if (t == 0) {
        float x = redm[0];
        for (int i = 1; i < 8; i++) x = fmaxf(x, redm[i]);
        redm[0] = x;
    }
    __syncthreads();
    m = redm[0];
    float e = __expf(v - m);
    float ssum = e;
#pragma unroll
    for (int o = 16; o; o >>= 1) ssum += __shfl_xor_sync(0xFFFFFFFFu, ssum, o);
    if ((t & 31) == 0) reds[t >> 5] = ssum;
    __syncthreads();
    if (t == 0) {
        float x = 0.0f;
        for (int i = 0; i < 8; i++) x += reds[i];
        reds[0] = x;
    }
    __syncthreads();
    g_att[n * LSEQ + t] = e / reds[0];
}

// ---------------- pooled = sum_l feat*att / 6 ----------------
__global__ void k_pool()
{
    __shared__ float at[LSEQ];
    int n = blockIdx.x, t = threadIdx.x;
    at[t] = g_att[n * LSEQ + t];
    __syncthreads();
    for (int d = t; d < DFEAT; d += 256) {
        float s = 0.0f;
        const float* f = g_feat + (size_t)n * LSEQ * DFEAT + d;
#pragma unroll 4
        for (int l = 0; l < LSEQ; l++) s += f[(size_t)l * DFEAT] * at[l];
        g_pool[n * DFEAT + d] = s * (1.0f / 6.0f);
    }
}

// ---------------- broadcast outputs ----------------
__global__ void k_out(float* __restrict__ out)
{
    const size_t n_logit = (size_t)NBATCH * LSEQ * NCLS;
    const size_t total = n_logit + (size_t)NBATCH * LSEQ * DFEAT;
    size_t i = (size_t)blockIdx.x * blockDim.x + threadIdx.x;
    size_t stride = (size_t)gridDim.x * blockDim.x;
    for (; i < total; i += stride) {
        if (i < n_logit) {
            size_t nl = i / NCLS; int c = (int)(i - nl * NCLS);
            int n = (int)(nl / LSEQ);
            out[i] = g_logits[n * NCLS + c];
        } else {
            size_t j = i - n_logit;
            size_t nl = j / DFEAT; int d = (int)(j - nl * DFEAT);
            int n = (int)(nl / LSEQ);
            out[i] = g_pool[n * DFEAT + d];
        }
    }
}

// ---------------- host launch ----------------
extern "C" void kernel_launch(void* const* d_in, const int* in_sizes, int n_in,
                              void* d_out, int out_size)
{
    const int*   sentence = (const int*)d_in[0];
    const int*   aspect   = (const int*)d_in[1];
    const int*   text_len = (const int*)d_in[2];
    const float* emb      = (const float*)d_in[3];
    const float* wih_f    = (const float*)d_in[4];
    const float* whh_f    = (const float*)d_in[5];
    const float* bih_f    = (const float*)d_in[6];
    const float* bhh_f    = (const float*)d_in[7];
    const float* wih_b    = (const float*)d_in[8];
    const float* whh_b    = (const float*)d_in[9];
    const float* bih_b    = (const float*)d_in[10];
    const float* bhh_b    = (const float*)d_in[11];
    const float* b1       = (const float*)d_in[13];
    const float* b2       = (const float*)d_in[15];
    const float* bf       = (const float*)d_in[17];
    float* out = (float*)d_out;

    float *pX, *pxg, *pWt, *pBias, *pW1t, *pW2t, *pWft, *pPool, *pX1, *pX2, *pLogits;
    cudaGetSymbolAddress((void**)&pX, g_X);
    cudaGetSymbolAddress((void**)&pxg, g_xg);
    cudaGetSymbolAddress((void**)&pWt, g_Wt);
    cudaGetSymbolAddress((void**)&pBias, g_bias);
    cudaGetSymbolAddress((void**)&pW1t, g_W1t);
    cudaGetSymbolAddress((void**)&pW2t, g_W2t);
    cudaGetSymbolAddress((void**)&pWft, g_Wft);
    cudaGetSymbolAddress((void**)&pPool, g_pool);
    cudaGetSymbolAddress((void**)&pX1, g_x1);
    cudaGetSymbolAddress((void**)&pX2, g_x2);
    cudaGetSymbolAddress((void**)&pLogits, g_logits);

    static int smem_set = 0;
    int recur_smem = (24 * WSTR + 64 * HSTR + 64 * 25 + 64 * 25 + 64 * 6 + 64 * 6) * 4;
    if (!smem_set) {
        cudaFuncSetAttribute(k_recur, cudaFuncAttributeMaxDynamicSharedMemorySize, recur_smem);
        smem_set = 1;
    }

    k_prep<<<512, 256>>>(wih_f, wih_b, bih_f, bhh_f, bih_b, bhh_b,
                         (const float*)d_in[12], (const float*)d_in[14], (const float*)d_in[16]);
    k_gather<<<2048, 256>>>(sentence, aspect, emb);

    dim3 ggrid(MROWS / BM, G4 / BN);
    k_gemm<<<ggrid, 256>>>(pX, KP, pWt, G4, pBias, pxg, G4, MROWS, G4, KP, 0);
    k_gemm<<<ggrid, 256>>>(pX, KP, pWt + (size_t)KP * G4, G4, pBias + G4,
                           pxg + (size_t)MROWS * G4, G4, MROWS, G4, KP, 0);

    k_recur<<<128, 256, recur_smem>>>(whh_f, whh_b);

    k_dots<<<dim3(NBATCH, LSEQ / 8), 256>>>();
    k_softmax<<<NBATCH, 256>>>(text_len);
    k_pool<<<NBATCH, 256>>>();

    k_gemm<<<dim3(1, FIN / BN), 256>>>(pPool, DFEAT, pW1t, FIN, b1, pX1, FIN, NBATCH, FIN, DFEAT, 1);
    k_gemm<<<dim3(1, FIN / BN), 256>>>(pX1, FIN, pW2t, FIN, b2, pX2, FIN, NBATCH, FIN, FIN, 1);
    k_gemm<<<dim3(1, 1), 256>>>(pX2, FIN, pWft, 128, bf, pLogits, NCLS, NBATCH, NCLS, FIN, 0);

    k_out<<<4096, 256>>>(out);
}

// round 13
// speedup vs baseline: 1.0961x; 1.0961x over previous
#include <cuda_runtime.h>
#include <cuda_bf16.h>
#include <cstddef>
#include <cstdint>

#define NBATCH 64
#define LSEQ   256
#define LASP   8
#define EMB    300
#define KP     320
#define HID    384
#define G4     1536
#define DFEAT  768
#define FIN    768
#define NCLS   3
#define SROWS  (NBATCH*LSEQ)
#define AROWS  (NBATCH*LASP)
#define MROWS  (SROWS+AROWS)

// ---------------- device scratch (static; no runtime allocation) ----------------
__device__ __align__(128) float g_X[MROWS * KP];
__device__ __align__(128) float g_xg[2 * MROWS * G4];
__device__ __align__(128) float g_Wt[2 * KP * G4];
__device__ __align__(128) float g_bias[2 * G4];
__device__ __align__(128) float g_W1t[FIN * FIN];
__device__ __align__(128) float g_W2t[FIN * FIN];
__device__ __align__(128) float g_Wft[FIN * 128];
__device__ __align__(128) float g_feat[(size_t)SROWS * DFEAT];
__device__ __align__(128) float g_h[2 * 2 * NBATCH * HID];
__device__ __align__(128) float g_aspv[NBATCH * DFEAT];
__device__ __align__(128) float g_dot[NBATCH * LSEQ];
__device__ __align__(128) float g_att[NBATCH * LSEQ];
__device__ __align__(128) float g_pool[NBATCH * DFEAT];
__device__ __align__(128) float g_x1[NBATCH * FIN];
__device__ __align__(128) float g_x2[NBATCH * FIN];
__device__ __align__(128) float g_logits[NBATCH * NCLS];
__device__ unsigned int g_barv[64];   // per-dir counters at [0] and [32] (128B apart)

__device__ __forceinline__ float sigf(float x)   { return 1.0f / (1.0f + __expf(-x)); }
__device__ __forceinline__ float tanhfast(float x){ return 2.0f / (1.0f + __expf(-2.0f * x)) - 1.0f; }

// packed f32x2 FMA (Blackwell FFMA2 — only reachable via PTX)
__device__ __forceinline__ void fma2(unsigned long long& acc, unsigned long long a,
                                     unsigned long long b) {
    asm("fma.rn.f32x2 %0, %1, %2, %0;" : "+l"(acc) : "l"(a), "l"(b));
}
__device__ __forceinline__ unsigned long long pack2(float lo, float hi) {
    unsigned long long r;
    asm("mov.b64 %0, {%1, %2};" : "=l"(r) : "f"(lo), "f"(hi));
    return r;
}
__device__ __forceinline__ float2 unpack2(unsigned long long v) {
    float2 r;
    asm("mov.b64 {%0, %1}, %2;" : "=f"(r.x), "=f"(r.y) : "l"(v));
    return r;
}
__device__ __forceinline__ unsigned int ld_relaxed_u32(const unsigned int* p) {
    unsigned int v;
    asm volatile("ld.global.relaxed.gpu.u32 %0, [%1];" : "=r"(v) : "l"(p));
    return v;
}

// cp.async helpers
__device__ __forceinline__ void cp_async16(uint32_t dst, const void* src) {
    asm volatile("cp.async.cg.shared.global [%0], [%1], 16;\n" :: "r"(dst), "l"(src));
}
__device__ __forceinline__ void cp_async8(uint32_t dst, const void* src) {
    asm volatile("cp.async.ca.shared.global [%0], [%1], 8;\n" :: "r"(dst), "l"(src));
}
__device__ __forceinline__ void cp_commit() { asm volatile("cp.async.commit_group;\n" ::: "memory"); }
template<int N> __device__ __forceinline__ void cp_wait() {
    asm volatile("cp.async.wait_group %0;\n" :: "n"(N) : "memory");
}

// ---------------- prep ----------------
__global__ void k_prep(const float* __restrict__ wih_f, const float* __restrict__ wih_b,
                       const float* __restrict__ bih_f, const float* __restrict__ bhh_f,
                       const float* __restrict__ bih_b, const float* __restrict__ bhh_b,
                       const float* __restrict__ W1, const float* __restrict__ W2,
                       const float* __restrict__ Wf)
{
    int tid = blockIdx.x * blockDim.x + threadIdx.x;
    int stride = gridDim.x * blockDim.x;
    for (int i = tid; i < 2 * KP * G4; i += stride) {
        int d = i / (KP * G4);
        int r = i - d * (KP * G4);
        int k = r / G4, g = r - (r / G4) * G4;
        const float* w = d ? wih_b : wih_f;
        g_Wt[i] = (k < EMB) ? w[g * EMB + k] : 0.0f;
    }
    for (int i = tid; i < 2 * G4; i += stride) {
        int d = i / G4, g = i - d * G4;
        g_bias[i] = d ? (bih_b[g] + bhh_b[g]) : (bih_f[g] + bhh_f[g]);
    }
    for (int i = tid; i < FIN * FIN; i += stride) {
        int k = i / FIN, n = i - (i / FIN) * FIN;
        g_W1t[i] = W1[n * FIN + k];
        g_W2t[i] = W2[n * FIN + k];
    }
    for (int i = tid; i < FIN * 128; i += stride) {
        int k = i / 128, c = i - (i / 128) * 128;
        g_Wft[i] = (c < NCLS) ? Wf[c * FIN + k] : 0.0f;
    }
    if (tid < 64) g_barv[tid] = 0u;
}

// ---------------- gather embeddings (padded) + zero h state ----------------
__global__ void k_gather(const int* __restrict__ sentence, const int* __restrict__ aspect,
                         const float* __restrict__ emb)
{
    int tid = blockIdx.x * blockDim.x + threadIdx.x;
    int stride = gridDim.x * blockDim.x;
    for (int i = tid; i < MROWS * KP; i += stride) {
        int row = i / KP, k = i - row * KP;
        int tok = (row < SROWS) ? sentence[row] : aspect[row - SROWS];
        g_X[i] = (k < EMB) ? emb[(size_t)tok * EMB + k] : 0.0f;
    }
    for (int i = tid; i < 2 * 2 * NBATCH * HID; i += stride) g_h[i] = 0.0f;
}

// ---------------- fp32 GEMM 128x128x16, double-buffered + reg-prefetch + FFMA2 ----------------
#define BM 128
#define BN 128
#define BK 16

__global__ void __launch_bounds__(256, 2) k_gemm(
    const float* __restrict__ A, int lda,
    const float* __restrict__ Bt, int ldb,
    const float* __restrict__ bias,
    float* __restrict__ C, int ldc,
    int M, int Nn, int K, int relu)
{
    __shared__ float As[2][BK][BM + 4];
    __shared__ float Bs[2][BK][BN + 4];
    int t = threadIdx.x;
    int tx = t & 15, ty = t >> 4;
    int m0 = blockIdx.x * BM, n0 = blockIdx.y * BN;
    unsigned long long acc2[8][4];
#pragma unroll
    for (int i = 0; i < 8; i++)
#pragma unroll
        for (int j = 0; j < 4; j++) acc2[i][j] = 0ull;

    int arow[2], akq[2], bkk[2], bnq[2];
#pragma unroll
    for (int q = 0; q < 2; q++) {
        int f = t + 256 * q;
        arow[q] = f >> 2;  akq[q] = (f & 3) * 4;
        bkk[q]  = f >> 5;  bnq[q] = (f & 31) * 4;
    }

    int nkt = K / BK;
    float4 av[2], bv[2];
    {
#pragma unroll
        for (int q = 0; q < 2; q++) {
            int gm = m0 + arow[q];
            av[q] = (gm < M) ? *(const float4*)(A + (size_t)gm * lda + akq[q])
                             : make_float4(0.f, 0.f, 0.f, 0.f);
            bv[q] = *(const float4*)(Bt + (size_t)bkk[q] * ldb + n0 + bnq[q]);
        }
    }

    int p = 0;
    for (int kt = 0; kt < nkt; ++kt) {
#pragma unroll
        for (int q = 0; q < 2; q++) {
            As[p][akq[q] + 0][arow[q]] = av[q].x; As[p][akq[q] + 1][arow[q]] = av[q].y;
            As[p][akq[q] + 2][arow[q]] = av[q].z; As[p][akq[q] + 3][arow[q]] = av[q].w;
            *(float4*)&Bs[p][bkk[q]][bnq[q]] = bv[q];
        }
        __syncthreads();

        if (kt + 1 < nkt) {
            int k0 = (kt + 1) * BK;
#pragma unroll
            for (int q = 0; q < 2; q++) {
                int gm = m0 + arow[q];
                av[q] = (gm < M) ? *(const float4*)(A + (size_t)gm * lda + k0 + akq[q])
                                 : make_float4(0.f, 0.f, 0.f, 0.f);
                bv[q] = *(const float4*)(Bt + (size_t)(k0 + bkk[q]) * ldb + n0 + bnq[q]);
            }
        }

#pragma unroll
        for (int k = 0; k < BK; k++) {
            ulonglong2 b0 = *(ulonglong2*)&Bs[p][k][tx * 4];
            ulonglong2 b1 = *(ulonglong2*)&Bs[p][k][tx * 4 + 64];
            unsigned long long bp[4] = {b0.x, b0.y, b1.x, b1.y};
            float4 a0 = *(float4*)&As[p][k][ty * 8];
            float4 a1 = *(float4*)&As[p][k][ty * 8 + 4];
            float a[8] = {a0.x, a0.y, a0.z, a0.w, a1.x, a1.y, a1.z, a1.w};
#pragma unroll
            for (int i = 0; i < 8; i++) {
                unsigned long long as = pack2(a[i], a[i]);
#pragma unroll
                for (int j = 0; j < 4; j++)
                    fma2(acc2[i][j], as, bp[j]);
            }
        }
        p ^= 1;
    }
#pragma unroll
    for (int i = 0; i < 8; i++) {
        int gm = m0 + ty * 8 + i;
        if (gm < M) {
#pragma unroll
            for (int jp = 0; jp < 4; jp++) {
                float2 pv = unpack2(acc2[i][jp]);
                int col = tx * 4 + (jp < 2 ? jp * 2 : 64 + (jp - 2) * 2);
#pragma unroll
                for (int e = 0; e < 2; e++) {
                    int gn = n0 + col + e;
                    if (gn < Nn) {
                        float v = e ? pv.y : pv.x;
                        if (bias) v += bias[gn];
                        if (relu) v = fmaxf(v, 0.0f);
                        C[(size_t)gm * ldc + gn] = v;
                    }
                }
            }
        }
    }
}

// ---------------- persistent BiLSTM recurrence ----------------
#define HSTR 388
#define WSTR 400
#define XSTR 26

__global__ void __launch_bounds__(256, 1) k_recur(const float* __restrict__ whhf,
                                                  const float* __restrict__ whhb)
{
    extern __shared__ float sm[];
    float* Ws = sm;                       // 24*400
    float* Hs = Ws + 24 * WSTR;           // 64*388
    float* Gs = Hs + 64 * HSTR;           // 64*25
    float* Xs = Gs + 64 * 25;             // 2 * 64*26 (double-buffered xg)

    const int t = threadIdx.x;
    const int cta = blockIdx.x;
    const int dir = cta >> 6;
    const int slice = cta & 63;
    const int u0 = slice * 6;
    const float* whh = dir ? whhb : whhf;
    const float* xgbase = g_xg + (size_t)dir * MROWS * G4;
    unsigned int* bar = &g_barv[dir * 32];

    const int kt = t & 3, rt = (t >> 2) & 3, ntid = t >> 4;
    const int n0 = ntid * 4;

    // stationary weights
    for (int i = t; i < 24 * HID; i += 256) {
        int lr = i / HID, k = i - lr * HID;
        int gate = lr & 3, u = lr >> 2;
        Ws[lr * WSTR + k] = whh[(size_t)(gate * HID + u0 + u) * HID + k];
    }
    __syncthreads();

    // h staging map (6 float4 per thread per chunk)
    int srows[6], scols[6];
    uint32_t sdst[6];
    uint32_t HsU = (uint32_t)__cvta_generic_to_shared(Hs);
#pragma unroll
    for (int pq = 0; pq < 6; pq++) {
        int idx = t + 256 * pq;
        srows[pq] = idx / 24;
        scols[pq] = idx - srows[pq] * 24;
        sdst[pq] = HsU + (uint32_t)(srows[pq] * HSTR + scols[pq] * 4) * 4u;
    }

    // xg prefetch map: thread handles (row, gate), 3x 8B = 24B
    const int xrow = t >> 2, xgate = t & 3;
    uint32_t XsU = (uint32_t)__cvta_generic_to_shared(Xs);

    // combine role: thread t<128 owns (cn, units cug..cug+2); state in registers
    const int cn = t >> 1, cug = (t & 1) * 3;
    float creg[3] = {0.f, 0.f, 0.f};
    float asum[3] = {0.f, 0.f, 0.f};

    int nb = 0;
    unsigned int tgt = 0;
    int sc = 0;

    // prologue: prefetch xg for (phase 0, s=0) into Xs buffer 0
    {
        int tt0 = dir ? (LSEQ - 1) : 0;
        const float* xp = xgbase + ((size_t)(xrow * LSEQ + tt0)) * G4 + xgate * HID + u0;
        uint32_t d = XsU + (uint32_t)((xrow * XSTR + xgate * 6) * 4);
        cp_async8(d, xp);
        cp_async8(d + 8, (const char*)xp + 8);
        cp_async8(d + 16, (const char*)xp + 16);
        cp_commit();
    }

    for (int phase = 0; phase < 2; ++phase) {
        const int T = phase ? LASP : LSEQ;
        for (int s = 0; s < T; ++s, ++sc) {
            const int tt = dir ? (T - 1 - s) : s;
            const int cur = sc & 1;

            // ---- issue h staging (4 groups) ----
            const float* hsrc = g_h + ((size_t)(nb * 2 + dir)) * NBATCH * HID;
#pragma unroll
            for (int c = 0; c < 4; c++) {
#pragma unroll
                for (int pq = 0; pq < 6; pq++) {
                    const float* src = hsrc + srows[pq] * HID + (c * 24 + scols[pq]) * 4;
                    cp_async16(sdst[pq] + (uint32_t)(c * 24 * 16), src);
                }
                cp_commit();
            }

            // ---- issue NEXT step's xg (group 5) into other Xs buffer ----
            {
                int np = phase, ns = s + 1;
                if (ns == T) { np = 1; ns = 0; }   // next phase start (or harmless dummy at very end)
                int Tn = np ? LASP : LSEQ;
                int ttn = dir ? (Tn - 1 - ns) : ns;
                size_t rown = np ? (size_t)(SROWS + xrow * LASP + ttn) : (size_t)(xrow * LSEQ + ttn);
                const float* xp = xgbase + rown * G4 + xgate * HID + u0;
                uint32_t d = XsU + (uint32_t)(((cur ^ 1) * 64 * XSTR + xrow * XSTR + xgate * 6) * 4);
                cp_async8(d, xp);
                cp_async8(d + 8, (const char*)xp + 8);
                cp_async8(d + 16, (const char*)xp + 16);
                cp_commit();
            }

            // ---- compute h @ W^T, pipelined chunks ----
            unsigned long long acc2[4][6];
#pragma unroll
            for (int i = 0; i < 4; i++)
#pragma unroll
                for (int j = 0; j < 6; j++) acc2[i][j] = 0ull;

#pragma unroll
            for (int c = 0; c < 4; c++) {
                if (c == 0) cp_wait<4>();
                else if (c == 1) cp_wait<3>();
                else if (c == 2) cp_wait<2>();
                else cp_wait<1>();
                __syncthreads();
#pragma unroll
                for (int it2 = 0; it2 < 6; it2++) {
                    int fk = (c * 24 + it2 * 4 + kt) * 4;
                    ulonglong2 hv[4], wv[6];
#pragma unroll
                    for (int i = 0; i < 4; i++)
                        hv[i] = *(const ulonglong2*)&Hs[(n0 + i) * HSTR + fk];
#pragma unroll
                    for (int j = 0; j < 6; j++)
                        wv[j] = *(const ulonglong2*)&Ws[(j * 4 + rt) * WSTR + fk];
#pragma unroll
                    for (int i = 0; i < 4; i++)
#pragma unroll
                        for (int j = 0; j < 6; j++) {
                            fma2(acc2[i][j], hv[i].x, wv[j].x);
                            fma2(acc2[i][j], hv[i].y, wv[j].y);
                        }
                }
            }

            // ---- reduce k-partials across kt lanes ----
#pragma unroll
            for (int i = 0; i < 4; i++)
#pragma unroll
                for (int j = 0; j < 6; j++) {
                    float2 pp = unpack2(acc2[i][j]);
                    float v = pp.x + pp.y;
                    v += __shfl_xor_sync(0xFFFFFFFFu, v, 1);
                    v += __shfl_xor_sync(0xFFFFFFFFu, v, 2);
                    if (kt == 0) Gs[(n0 + i) * 25 + rt * 6 + j] = v;
                }
            __syncthreads();

            // ---- combine: 128 threads, 3 units each, state in regs ----
            float hreg[3];
            if (t < 128) {
                const float* gb = Gs + cn * 25;
                const float* xr = Xs + cur * (64 * XSTR) + cn * XSTR;
                float* hout = g_h + ((size_t)(((nb ^ 1) * 2 + dir))) * NBATCH * HID + cn * HID + u0;
#pragma unroll
                for (int j = 0; j < 3; j++) {
                    int u = cug + j;
                    float gi = gb[u]      + xr[u];
                    float gf = gb[6 + u]  + xr[6 + u];
                    float gg = gb[12 + u] + xr[12 + u];
                    float go = gb[18 + u] + xr[18 + u];
                    float cc = sigf(gf) * creg[j] + sigf(gi) * tanhfast(gg);
                    float hh = sigf(go) * tanhfast(cc);
                    creg[j] = cc;
                    hreg[j] = hh;
                    hout[u] = hh;
                }
                __threadfence();
            }
            __syncthreads();
            tgt += 64;
            if (t == 0) {
                atomicAdd(bar, 1u);
                while (ld_relaxed_u32(bar) < tgt) { }
                __threadfence();
            }
            __syncthreads();

            // ---- post-barrier: feat / aspect-sum (off the critical path) ----
            if (t < 128) {
                if (phase == 0) {
#pragma unroll
                    for (int j = 0; j < 3; j++)
                        g_feat[(size_t)(cn * LSEQ + tt) * DFEAT + dir * HID + u0 + cug + j] = hreg[j];
                } else {
#pragma unroll
                    for (int j = 0; j < 3; j++) asum[j] += hreg[j];
                }
            }
            nb ^= 1;
        }
        if (phase == 0) {
            // reset h (buffer to be read next) and c-state before aspect pass
            if (t < 128) {
                float* hout = g_h + ((size_t)(nb * 2 + dir)) * NBATCH * HID + cn * HID + u0;
#pragma unroll
                for (int j = 0; j < 3; j++) { hout[cug + j] = 0.0f; creg[j] = 0.0f; }
                __threadfence();
            }
            __syncthreads();
            tgt += 64;
            if (t == 0) {
                atomicAdd(bar, 1u);
                while (ld_relaxed_u32(bar) < tgt) { }
                __threadfence();
            }
            __syncthreads();
        }
    }
    cp_wait<0>();
    if (t < 128) {
#pragma unroll
        for (int j = 0; j < 3; j++)
            g_aspv[cn * DFEAT + dir * HID + u0 + cug + j] = asum[j] * (1.0f / LASP);
    }
}

// ---------------- attention: dots ----------------
__global__ void k_dots()
{
    __shared__ float As2[DFEAT];
    int n = blockIdx.x;
    for (int i = threadIdx.x; i < DFEAT; i += 256) As2[i] = g_aspv[n * DFEAT + i];
    __syncthreads();
    int warp = threadIdx.x >> 5, lane = threadIdx.x & 31;
    int l = blockIdx.y * 8 + warp;
    const float* f = g_feat + (size_t)(n * LSEQ + l) * DFEAT;
    float s = 0.0f;
    for (int i = lane * 4; i < DFEAT; i += 128) {
        float4 fv = *(const float4*)(f + i);
        float4 av = *(const float4*)(&As2[i]);
        s += fv.x * av.x + fv.y * av.y + fv.z * av.z + fv.w * av.w;
    }
#pragma unroll
    for (int o = 16; o; o >>= 1) s += __shfl_xor_sync(0xFFFFFFFFu, s, o);
    if (lane == 0) g_dot[n * LSEQ + l] = s;
}

// ---------------- masked softmax over L ----------------
__global__ void k_softmax(const int* __restrict__ tl)
{
    __shared__ float redm[8];
    __shared__ float reds[8];
    int n = blockIdx.x, t = threadIdx.x;
    int len = tl[n];
    float d = g_dot[n * LSEQ + t];
    float v = (t < len) ? d : -1e30f;
    float m = v;
#pragma unroll
    for (int o = 16; o; o >>= 1) m = fmaxf(m, __shfl_xor_sync(0xFFFFFFFFu, m, o));
    if ((t & 31) == 0) redm[t >> 5] = m;
    __syncthreads();
    if (t == 0) {
        float x = redm[0];
        for (int i = 1; i < 8; i++) x = fmaxf(x, redm[i]);
        redm[0] = x;
    }
    __syncthreads();
    m = redm[0];
    float e = __expf(v - m);
    float ssum = e;
#pragma unroll
    for (int o = 16; o; o >>= 1) ssum += __shfl_xor_sync(0xFFFFFFFFu, ssum, o);
    if ((t & 31) == 0) reds[t >> 5] = ssum;
    __syncthreads();
    if (t == 0) {
        float x = 0.0f;
        for (int i = 0; i < 8; i++) x += reds[i];
        reds[0] = x;
    }
    __syncthreads();
    g_att[n * LSEQ + t] = e / reds[0];
}

// ---------------- pooled = sum_l feat*att / 6 ----------------
__global__ void k_pool()
{
    __shared__ float at[LSEQ];
    int n = blockIdx.x, t = threadIdx.x;
    at[t] = g_att[n * LSEQ + t];
    __syncthreads();
    for (int d = t; d < DFEAT; d += 256) {
        float s = 0.0f;
        const float* f = g_feat + (size_t)n * LSEQ * DFEAT + d;
#pragma unroll 4
        for (int l = 0; l < LSEQ; l++) s += f[(size_t)l * DFEAT] * at[l];
        g_pool[n * DFEAT + d] = s * (1.0f / 6.0f);
    }
}

// ---------------- broadcast outputs ----------------
__global__ void k_out(float* __restrict__ out)
{
    const size_t n_logit = (size_t)NBATCH * LSEQ * NCLS;
    const size_t total = n_logit + (size_t)NBATCH * LSEQ * DFEAT;
    size_t i = (size_t)blockIdx.x * blockDim.x + threadIdx.x;
    size_t stride = (size_t)gridDim.x * blockDim.x;
    for (; i < total; i += stride) {
        if (i < n_logit) {
            size_t nl = i / NCLS; int c = (int)(i - nl * NCLS);
            int n = (int)(nl / LSEQ);
            out[i] = g_logits[n * NCLS + c];
        } else {
            size_t j = i - n_logit;
            size_t nl = j / DFEAT; int d = (int)(j - nl * DFEAT);
            int n = (int)(nl / LSEQ);
            out[i] = g_pool[n * DFEAT + d];
        }
    }
}

// ---------------- host launch ----------------
extern "C" void kernel_launch(void* const* d_in, const int* in_sizes, int n_in,
                              void* d_out, int out_size)
{
    const int*   sentence = (const int*)d_in[0];
    const int*   aspect   = (const int*)d_in[1];
    const int*   text_len = (const int*)d_in[2];
    const float* emb      = (const float*)d_in[3];
    const float* wih_f    = (const float*)d_in[4];
    const float* whh_f    = (const float*)d_in[5];
    const float* bih_f    = (const float*)d_in[6];
    const float* bhh_f    = (const float*)d_in[7];
    const float* wih_b    = (const float*)d_in[8];
    const float* whh_b    = (const float*)d_in[9];
    const float* bih_b    = (const float*)d_in[10];
    const float* bhh_b    = (const float*)d_in[11];
    const float* b1       = (const float*)d_in[13];
    const float* b2       = (const float*)d_in[15];
    const float* bf       = (const float*)d_in[17];
    float* out = (float*)d_out;

    float *pX, *pxg, *pWt, *pBias, *pW1t, *pW2t, *pWft, *pPool, *pX1, *pX2, *pLogits;
    cudaGetSymbolAddress((void**)&pX, g_X);
    cudaGetSymbolAddress((void**)&pxg, g_xg);
    cudaGetSymbolAddress((void**)&pWt, g_Wt);
    cudaGetSymbolAddress((void**)&pBias, g_bias);
    cudaGetSymbolAddress((void**)&pW1t, g_W1t);
    cudaGetSymbolAddress((void**)&pW2t, g_W2t);
    cudaGetSymbolAddress((void**)&pWft, g_Wft);
    cudaGetSymbolAddress((void**)&pPool, g_pool);
    cudaGetSymbolAddress((void**)&pX1, g_x1);
    cudaGetSymbolAddress((void**)&pX2, g_x2);
    cudaGetSymbolAddress((void**)&pLogits, g_logits);

    static int smem_set = 0;
    int recur_smem = (24 * WSTR + 64 * HSTR + 64 * 25 + 2 * 64 * XSTR) * 4;
    if (!smem_set) {
        cudaFuncSetAttribute(k_recur, cudaFuncAttributeMaxDynamicSharedMemorySize, recur_smem);
        smem_set = 1;
    }

    k_prep<<<512, 256>>>(wih_f, wih_b, bih_f, bhh_f, bih_b, bhh_b,
                         (const float*)d_in[12], (const float*)d_in[14], (const float*)d_in[16]);
    k_gather<<<2048, 256>>>(sentence, aspect, emb);

    dim3 ggrid(MROWS / BM, G4 / BN);
    k_gemm<<<ggrid, 256>>>(pX, KP, pWt, G4, pBias, pxg, G4, MROWS, G4, KP, 0);
    k_gemm<<<ggrid, 256>>>(pX, KP, pWt + (size_t)KP * G4, G4, pBias + G4,
                           pxg + (size_t)MROWS * G4, G4, MROWS, G4, KP, 0);

    k_recur<<<128, 256, recur_smem>>>(whh_f, whh_b);

    k_dots<<<dim3(NBATCH, LSEQ / 8), 256>>>();
    k_softmax<<<NBATCH, 256>>>(text_len);
    k_pool<<<NBATCH, 256>>>();

    k_gemm<<<dim3(1, FIN / BN), 256>>>(pPool, DFEAT, pW1t, FIN, b1, pX1, FIN, NBATCH, FIN, DFEAT, 1);
    k_gemm<<<dim3(1, FIN / BN), 256>>>(pX1, FIN, pW2t, FIN, b2, pX2, FIN, NBATCH, FIN, FIN, 1);
    k_gemm<<<dim3(1, 1), 256>>>(pX2, FIN, pWft, 128, bf, pLogits, NCLS, NBATCH, NCLS, FIN, 0);

    k_out<<<4096, 256>>>(out);
}